// round 5
// baseline (speedup 1.0000x reference)
#include <cuda_runtime.h>
#include <math.h>
#include <stdint.h>

// ---------------- problem constants ----------------
#define Nn 262144
#define Dd 64
#define Kk 64
#define NB 72            // MMA N: 64 clusters + 1 background col + 7 pad
#define TM 256           // rows per CTA
#define NTILES (Nn/TM)   // 1024
#define TPB 256
#define LOG2PI_F 1.83787706640934548356f
#define PLV0 (-2.0f)

// ---------------- device globals (no allocs allowed) ----------------
__device__ float  g_Bplain[NB*128];  // [n][k]: k<64 -> -2*mu*a ; 64+d -> a (n=64: bg wts)
__device__ float  g_Bpack[9*8*32*4]; // fragment-packed B: [j][oct][lane] = float4
__device__ float  g_offs[Kk];
__device__ float  g_logpi[Kk];
__device__ float  g_C0;
__device__ double g_kl;
__device__ double g_lse;
__device__ unsigned int g_count;

__device__ __forceinline__ float tf32r(float x) {
    float r; asm("cvt.rna.tf32.f32 %0, %1;" : "=f"(r) : "f"(x)); return r;
}

__device__ __forceinline__ void mma8(float c[4],
                                     uint32_t a0, uint32_t a1, uint32_t a2, uint32_t a3,
                                     uint32_t b0, uint32_t b1) {
    asm volatile("mma.sync.aligned.m16n8k8.row.col.f32.tf32.tf32.f32 "
        "{%0,%1,%2,%3}, {%4,%5,%6,%7}, {%8,%9}, {%0,%1,%2,%3};"
        : "+f"(c[0]), "+f"(c[1]), "+f"(c[2]), "+f"(c[3])
        : "r"(a0), "r"(a1), "r"(a2), "r"(a3), "r"(b0), "r"(b1));
}

// ---------------------------------------------------------------------------
// Kernel 1: precompute (1 block x 1024 threads).
// ---------------------------------------------------------------------------
__global__ void precompute_kernel(const float* __restrict__ u_noise,
                                  const float* __restrict__ phi_logits,
                                  const float* __restrict__ q_mu,
                                  const float* __restrict__ q_logvar,
                                  const float* __restrict__ pi_logits,
                                  const float* __restrict__ prior_p,
                                  float* __restrict__ out)
{
    __shared__ float phi_s[64], red[64], red2[64], pil_s[64], ex_s[64];
    __shared__ float obuf[Kk*Dd];
    int t = threadIdx.x;

    if (t < 64) {
        float uu  = u_noise[t];
        float g   = -__logf(-__logf(uu + 1e-9f) + 1e-9f);
        float pl  = phi_logits[t];
        float phi = 1.0f / (1.0f + __expf(-(pl + g)));
        phi_s[t]  = phi;
        float qphi = 1.0f / (1.0f + __expf(-pl));
        qphi = fminf(fmaxf(qphi, 1e-6f), 1.0f - 1e-6f);
        out[1 + t] = qphi;
        float p = fminf(fmaxf(prior_p[t], 1e-6f), 1.0f - 1e-6f);
        red[t]  = qphi * (__logf(qphi) - __logf(p))
                + (1.0f - qphi) * (__logf(1.0f - qphi) - __logf(1.0f - p));
        red2[t] = (1.0f - phi) * (LOG2PI_F + PLV0);
        pil_s[t] = pi_logits[t];
    }
    __syncthreads();
    if (t < 64) {
        float a = red[t], b = red2[t];
        #pragma unroll
        for (int s = 16; s; s >>= 1) {
            a += __shfl_xor_sync(0xffffffffu, a, s);
            b += __shfl_xor_sync(0xffffffffu, b, s);
        }
        if ((t & 31) == 0) { red[t >> 5] = a; red2[t >> 5] = b; }
    }
    __syncthreads();
    if (t == 0) {
        g_kl  = (double)(red[0] + red[1]) * (double)Nn;
        g_C0  = red2[0] + red2[1];
        g_lse = 0.0;
        g_count = 0u;
    }
    if (t < 64) {
        float m = pil_s[t];
        #pragma unroll
        for (int s = 16; s; s >>= 1) m = fmaxf(m, __shfl_xor_sync(0xffffffffu, m, s));
        if ((t & 31) == 0) ex_s[t >> 5] = m;
    }
    __syncthreads();
    if (t < 64) {
        float m = fmaxf(ex_s[0], ex_s[1]);
        float e = __expf(pil_s[t] - m);
        red[t] = e;
        float ss = e;
        #pragma unroll
        for (int s = 16; s; s >>= 1) ss += __shfl_xor_sync(0xffffffffu, ss, s);
        if ((t & 31) == 0) ex_s[(t >> 5) + 2] = ss;
    }
    __syncthreads();
    if (t < 64) g_logpi[t] = __logf(red[t] / (ex_s[2] + ex_s[3]) + 1e-9f);

    // plain B matrix [72][128], tf32-rounded
    for (int idx = t; idx < NB * 128; idx += 1024) {
        int n = idx >> 7, k = idx & 127;
        int d = k & 63, isq = k >> 6;
        float val = 0.f;
        if (n < Kk) {
            float lvc = fminf(fmaxf(q_logvar[n * Dd + d], -5.0f), 5.0f);
            float a   = phi_s[d] * __expf(-lvc);
            float mu  = q_mu[n * Dd + d];
            if (isq) {
                val = a;
                obuf[n * Dd + d] = phi_s[d] * (LOG2PI_F + lvc) + mu * mu * a;
            } else {
                val = -2.0f * mu * a;
            }
            val = tf32r(val);
        } else if (n == Kk && isq) {
            val = tf32r((1.0f - phi_s[d]) * __expf(-PLV0));  // background column
        }
        g_Bplain[idx] = val;
    }
    __syncthreads();   // also orders global writes within the block

    // pack B into mma fragment order: id = (j*8+oct)*32+lane ->
    // float4 { Blin[n][k0+t4], Blin[n][k0+t4+4], Bq[n][k0+t4], Bq[n][k0+t4+4] }
    for (int id = t; id < 9 * 8 * 32; id += 1024) {
        int lane = id & 31, oct = (id >> 5) & 7, j = id >> 8;
        int n = 8 * j + (lane >> 2), t4 = lane & 3, k0 = oct * 8;
        const float* bn = g_Bplain + n * 128;
        float4 v;
        v.x = bn[k0 + t4];
        v.y = bn[k0 + t4 + 4];
        v.z = bn[64 + k0 + t4];
        v.w = bn[64 + k0 + t4 + 4];
        *(float4*)(g_Bpack + 4 * id) = v;
    }
    __syncthreads();
    if (t < 256) {
        int k = t & 63, part = t >> 6;
        float s = 0.f;
        #pragma unroll
        for (int d = part * 16; d < part * 16 + 16; d++) s += obuf[k * Dd + d];
        __syncthreads();
        obuf[part * 64 + k] = s;
    } else {
        __syncthreads();
    }
    __syncthreads();
    if (t < 64)
        g_offs[t] = -0.5f * (obuf[t] + obuf[64 + t] + obuf[128 + t] + obuf[192 + t]);
}

// ---------------------------------------------------------------------------
// Kernel 2: main pass. CTA = 256 rows, 8 warps; warp = m32 x n72 (two m16
// tiles share each B fragment). B fragments pre-packed -> 1 LDS.128 each.
// ---------------------------------------------------------------------------
#define ASTR 68
#define OFF_A    0
#define OFF_B    69632
#define OFF_OFFS 106496
#define OFF_LPI  106752
#define SMEM_BYTES 107264

__global__ void __launch_bounds__(TPB, 2)
main_kernel(const float* __restrict__ X, float* __restrict__ out)
{
    extern __shared__ char smem[];
    float* A_s    = (float*)(smem + OFF_A);     // 256 x 68 (k=0..63 used)
    float* B_s    = (float*)(smem + OFF_B);     // packed fragments, 36864B
    float* offs_s = (float*)(smem + OFF_OFFS);
    float* lpi_s  = (float*)(smem + OFF_LPI);
    __shared__ double wsum[TPB / 32];

    const int tid = threadIdx.x, wid = tid >> 5, lane = tid & 31;
    const int g = lane >> 2, t4 = lane & 3;
    const int n0 = blockIdx.x * TM;

    // stage packed B (straight float4 copy: 2304 float4s)
    #pragma unroll
    for (int it = 0; it < 9; it++) {
        int i4 = tid + TPB * it;
        *((float4*)B_s + i4) = *((const float4*)g_Bpack + i4);
    }
    if (tid < 64) { offs_s[tid] = g_offs[tid]; lpi_s[tid] = g_logpi[tid]; }

    // stage X tile (256x64), tf32-rounded
    #pragma unroll
    for (int it = 0; it < 16; it++) {
        int i4 = tid + TPB * it;   // 4096 float4s
        int m = i4 >> 4, kq = (i4 & 15) << 2;
        float4 v = *(const float4*)(X + (size_t)(n0 + m) * Dd + kq);
        v.x = tf32r(v.x); v.y = tf32r(v.y); v.z = tf32r(v.z); v.w = tf32r(v.w);
        *(float4*)(A_s + m * ASTR + kq) = v;
    }
    __syncthreads();

    float c[2][9][4];
    #pragma unroll
    for (int u = 0; u < 2; u++)
        #pragma unroll
        for (int j = 0; j < 9; j++)
            { c[u][j][0] = 0.f; c[u][j][1] = 0.f; c[u][j][2] = 0.f; c[u][j][3] = 0.f; }

    const float* aptr = A_s + (32 * wid + g) * ASTR + t4;
    const float4* bw  = (const float4*)B_s + lane;

    #pragma unroll
    for (int k0 = 0; k0 < 64; k0 += 8) {
        // A fragments for two m16 tiles (rows +0,+8 and +16,+24)
        float f00 = aptr[k0],             f01 = aptr[8  * ASTR + k0];
        float f02 = aptr[k0 + 4],         f03 = aptr[8  * ASTR + k0 + 4];
        float f10 = aptr[16 * ASTR + k0], f11 = aptr[24 * ASTR + k0];
        float f12 = aptr[16 * ASTR + k0 + 4], f13 = aptr[24 * ASTR + k0 + 4];
        uint32_t a00 = __float_as_uint(f00), a01 = __float_as_uint(f01);
        uint32_t a02 = __float_as_uint(f02), a03 = __float_as_uint(f03);
        uint32_t a10 = __float_as_uint(f10), a11 = __float_as_uint(f11);
        uint32_t a12 = __float_as_uint(f12), a13 = __float_as_uint(f13);
        uint32_t q00 = __float_as_uint(tf32r(f00 * f00));
        uint32_t q01 = __float_as_uint(tf32r(f01 * f01));
        uint32_t q02 = __float_as_uint(tf32r(f02 * f02));
        uint32_t q03 = __float_as_uint(tf32r(f03 * f03));
        uint32_t q10 = __float_as_uint(tf32r(f10 * f10));
        uint32_t q11 = __float_as_uint(tf32r(f11 * f11));
        uint32_t q12 = __float_as_uint(tf32r(f12 * f12));
        uint32_t q13 = __float_as_uint(tf32r(f13 * f13));

        const int oct = k0 >> 3;
        #pragma unroll
        for (int j = 0; j < 9; j++) {
            float4 b = bw[(j * 8 + oct) * 32];
            uint32_t b0 = __float_as_uint(b.x), b1 = __float_as_uint(b.y);
            uint32_t e0 = __float_as_uint(b.z), e1 = __float_as_uint(b.w);
            mma8(c[0][j], a00, a01, a02, a03, b0, b1);
            mma8(c[0][j], q00, q01, q02, q03, e0, e1);
            mma8(c[1][j], a10, a11, a12, a13, b0, b1);
            mma8(c[1][j], q10, q11, q12, q13, e0, e1);
        }
    }

    // ---------------- epilogue ----------------
    const float C0 = g_C0;
    double lsesum = 0.0;
    #pragma unroll
    for (int u = 0; u < 2; u++) {
        #pragma unroll
        for (int h = 0; h < 2; h++) {
            int r = 32 * wid + 16 * u + 8 * h + g;     // local row
            float bgq  = __shfl_sync(0xffffffffu, c[u][8][2 * h], lane & ~3);
            float lpbg = -0.5f * (C0 + bgq);
            float lp[16];
            float mx = -3.4e38f;
            #pragma unroll
            for (int j = 0; j < 8; j++) {
                int col = 8 * j + 2 * t4;
                float v0 = fmaf(-0.5f, c[u][j][2 * h],     offs_s[col])     + lpbg;
                float v1 = fmaf(-0.5f, c[u][j][2 * h + 1], offs_s[col + 1]) + lpbg;
                lp[2 * j] = v0; lp[2 * j + 1] = v1;
                mx = fmaxf(mx, fmaxf(v0 + lpi_s[col], v1 + lpi_s[col + 1]));
            }
            mx = fmaxf(mx, __shfl_xor_sync(0xffffffffu, mx, 1));
            mx = fmaxf(mx, __shfl_xor_sync(0xffffffffu, mx, 2));
            float se = 0.f;
            #pragma unroll
            for (int j = 0; j < 8; j++) {
                int col = 8 * j + 2 * t4;
                se += __expf(lp[2 * j]     + lpi_s[col]     - mx);
                se += __expf(lp[2 * j + 1] + lpi_s[col + 1] - mx);
            }
            se += __shfl_xor_sync(0xffffffffu, se, 1);
            se += __shfl_xor_sync(0xffffffffu, se, 2);
            if (t4 == 0) lsesum += (double)(mx + __logf(se));
            // stage lp into this warp's own A rows (done reading them)
            float* srow = A_s + r * ASTR + 2 * t4;
            #pragma unroll
            for (int j = 0; j < 8; j++)
                *(float2*)(srow + 8 * j) = make_float2(lp[2 * j], lp[2 * j + 1]);
        }
    }

    // block-level lse reduce -> ONE atomic per block
    #pragma unroll
    for (int s = 16; s; s >>= 1)
        lsesum += __shfl_xor_sync(0xffffffffu, lsesum, s);
    if (lane == 0) wsum[wid] = lsesum;

    __syncthreads();
    // coalesced copy of staged lp (out+65 is 4B-aligned only -> scalar)
    float* obase = out + 65 + (size_t)n0 * Kk;
    #pragma unroll
    for (int i = 0; i < 64; i++) {
        int idx = tid + TPB * i;                       // 16384 floats
        obase[idx] = A_s[(idx >> 6) * ASTR + (idx & 63)];
    }

    // last-block finalize: write loss, reset accumulators for next replay
    if (tid == 0) {
        double bsum = 0.0;
        #pragma unroll
        for (int w = 0; w < TPB / 32; w++) bsum += wsum[w];
        atomicAdd(&g_lse, bsum);
        __threadfence();
        unsigned int old = atomicAdd(&g_count, 1u);
        if (old == NTILES - 1) {
            double total = atomicAdd(&g_lse, 0.0);
            out[0] = (float)(g_kl - total);
            g_lse = 0.0;
            g_count = 0u;
        }
    }
}

// ---------------------------------------------------------------------------
extern "C" void kernel_launch(void* const* d_in, const int* in_sizes, int n_in,
                              void* d_out, int out_size)
{
    const float* X  = (const float*)d_in[0];
    const float* u  = (const float*)d_in[1];
    const float* pl = (const float*)d_in[2];
    const float* mu = (const float*)d_in[3];
    const float* lv = (const float*)d_in[4];
    const float* pi = (const float*)d_in[5];
    const float* pp = (const float*)d_in[6];
    float* out = (float*)d_out;

    cudaFuncSetAttribute(main_kernel,
                         cudaFuncAttributeMaxDynamicSharedMemorySize, SMEM_BYTES);

    precompute_kernel<<<1, 1024>>>(u, pl, mu, lv, pi, pp, out);
    main_kernel<<<NTILES, TPB, SMEM_BYTES>>>(X, out);
}

// round 6
// speedup vs baseline: 1.1401x; 1.1401x over previous
#include <cuda_runtime.h>
#include <math.h>
#include <stdint.h>

// ---------------- problem constants ----------------
#define Nn 262144
#define Dd 64
#define Kk 64
#define TM 128             // rows per tile
#define NT (Nn/TM)         // 2048 tiles
#define TPB 256
#define GRID 296           // persistent CTAs (2 per SM x 148)
#define LOG2PI_F 1.83787706640934548356f
#define EXP2_F 7.389056098930650f   // exp(2) = exp(-PLV0), PLV0 = -2
#define ASTR 68

// ---------------- device globals ----------------
__device__ double g_lse;           // zero-init at load; reset by last CTA each run
__device__ unsigned int g_count;

__device__ __forceinline__ float tf32r(float x) {
    float r; asm("cvt.rna.tf32.f32 %0, %1;" : "=f"(r) : "f"(x)); return r;
}
__device__ __forceinline__ void mma8(float c[4],
                                     uint32_t a0, uint32_t a1, uint32_t a2, uint32_t a3,
                                     uint32_t b0, uint32_t b1) {
    asm volatile("mma.sync.aligned.m16n8k8.row.col.f32.tf32.tf32.f32 "
        "{%0,%1,%2,%3}, {%4,%5,%6,%7}, {%8,%9}, {%0,%1,%2,%3};"
        : "+f"(c[0]), "+f"(c[1]), "+f"(c[2]), "+f"(c[3])
        : "r"(a0), "r"(a1), "r"(a2), "r"(a3), "r"(b0), "r"(b1));
}

#define CP_COMMIT() asm volatile("cp.async.commit_group;" ::: "memory")
#define CP_WAIT1()  asm volatile("cp.async.wait_group 1;"  ::: "memory")

__device__ __forceinline__ void prefetch_tile(const float* __restrict__ X,
                                              int tile, float* dst, int tid) {
    const char* src = (const char*)(X + (size_t)tile * TM * Dd);
    #pragma unroll
    for (int it = 0; it < 8; it++) {
        int i4 = tid + TPB * it;               // 2048 float4s per tile
        int m = i4 >> 4, q = i4 & 15;
        uint32_t d = (uint32_t)__cvta_generic_to_shared(
            (const char*)dst + (size_t)m * (ASTR * 4) + q * 16);
        asm volatile("cp.async.cg.shared.global [%0], [%1], 16;"
                     :: "r"(d), "l"(src + (size_t)i4 * 16));
    }
}

// ---------------------------------------------------------------------------
// Single persistent kernel: in-CTA precompute + double-buffered tile loop.
// Warp = m16 x n72 (c[9][4]); B pre-packed in fragment order (1 LDS.128).
// ---------------------------------------------------------------------------
#define SMEM_FLOATS (2*TM*ASTR + 9*8*32*4 + 64 + 64)
#define SMEM_BYTES  (SMEM_FLOATS * 4)          // 107008

__global__ void __launch_bounds__(TPB, 2)
gmm_kernel(const float* __restrict__ X,
           const float* __restrict__ u_noise,
           const float* __restrict__ phi_logits,
           const float* __restrict__ q_mu,
           const float* __restrict__ q_logvar,
           const float* __restrict__ pi_logits,
           const float* __restrict__ prior_p,
           float* __restrict__ out)
{
    extern __shared__ float smem[];
    float* Abuf0  = smem;                        // 128*68
    float* Abuf1  = smem + TM * ASTR;            // 128*68
    float* B_s    = smem + 2 * TM * ASTR;        // 9216 floats (packed frags)
    float* offs_s = B_s + 9216;                  // 64
    float* lpi_s  = offs_s + 64;                 // 64

    __shared__ float phi_s[64], scr[256];
    __shared__ float kl_s, c0_s;
    __shared__ double wsum[TPB / 32];

    const int tid = threadIdx.x, wid = tid >> 5, lane = tid & 31;
    const int g = lane >> 2, t4 = lane & 3;

    // ---- kick off first tile load immediately ----
    int tile = blockIdx.x;
    if (tile < NT) prefetch_tile(X, tile, Abuf0, tid);
    CP_COMMIT();

    // ---- in-CTA precompute (overlaps the prefetch) ----
    if (tid < 64) {
        float uu  = u_noise[tid];
        float gmb = -__logf(-__logf(uu + 1e-9f) + 1e-9f);
        float pl  = phi_logits[tid];
        float phi = 1.0f / (1.0f + __expf(-(pl + gmb)));
        phi_s[tid] = phi;
        float qphi = 1.0f / (1.0f + __expf(-pl));
        qphi = fminf(fmaxf(qphi, 1e-6f), 1.0f - 1e-6f);
        if (blockIdx.x == 0) out[1 + tid] = qphi;
        float p = fminf(fmaxf(prior_p[tid], 1e-6f), 1.0f - 1e-6f);
        scr[tid]       = qphi * (__logf(qphi) - __logf(p))
                       + (1.0f - qphi) * (__logf(1.0f - qphi) - __logf(1.0f - p));
        scr[64 + tid]  = (1.0f - phi) * (LOG2PI_F - 2.0f);
        scr[128 + tid] = pi_logits[tid];
    }
    __syncthreads();
    if (tid == 0) {
        float kl = 0.f, c0 = 0.f;
        #pragma unroll
        for (int i = 0; i < 64; i++) { kl += scr[i]; c0 += scr[64 + i]; }
        kl_s = kl; c0_s = c0;
    }
    if (tid < 64) {   // log softmax(pi)+1e-9 (broadcast smem reads)
        float m = -3.4e38f;
        #pragma unroll
        for (int k = 0; k < 64; k++) m = fmaxf(m, scr[128 + k]);
        float ss = 0.f;
        #pragma unroll
        for (int k = 0; k < 64; k++) ss += __expf(scr[128 + k] - m);
        lpi_s[tid] = __logf(__expf(scr[128 + tid] - m) / ss + 1e-9f);
    }
    __syncthreads();

    // ---- build packed B fragments directly ----
    #pragma unroll
    for (int it = 0; it < 9; it++) {
        int id = tid + TPB * it;                 // 2304 entries
        int ln = id & 31, oct = (id >> 5) & 7, j = id >> 8;
        int n = 8 * j + (ln >> 2), d1 = oct * 8 + (ln & 3), d2 = d1 + 4;
        float4 v = make_float4(0.f, 0.f, 0.f, 0.f);
        if (n < Kk) {
            float lv1 = fminf(fmaxf(q_logvar[n * Dd + d1], -5.0f), 5.0f);
            float lv2 = fminf(fmaxf(q_logvar[n * Dd + d2], -5.0f), 5.0f);
            float a1 = phi_s[d1] * __expf(-lv1);
            float a2 = phi_s[d2] * __expf(-lv2);
            v.x = tf32r(-2.0f * q_mu[n * Dd + d1] * a1);
            v.y = tf32r(-2.0f * q_mu[n * Dd + d2] * a2);
            v.z = tf32r(a1);
            v.w = tf32r(a2);
        } else if (n == Kk) {
            v.z = tf32r((1.0f - phi_s[d1]) * EXP2_F);
            v.w = tf32r((1.0f - phi_s[d2]) * EXP2_F);
        }
        *((float4*)B_s + id) = v;
    }
    // offs partials: 4 partial sums of 16 dims per cluster
    {
        int n = tid & 63, part = tid >> 6;
        float s = 0.f;
        #pragma unroll
        for (int d = part * 16; d < part * 16 + 16; d++) {
            float lv = fminf(fmaxf(q_logvar[n * Dd + d], -5.0f), 5.0f);
            float a  = phi_s[d] * __expf(-lv);
            float mu = q_mu[n * Dd + d];
            s += phi_s[d] * (LOG2PI_F + lv) + mu * mu * a;
        }
        __syncthreads();     // scr free (kl/logpi consumed)
        scr[tid] = s;
    }
    __syncthreads();
    if (tid < 64)
        offs_s[tid] = -0.5f * (scr[tid] + scr[64 + tid] + scr[128 + tid] + scr[192 + tid]);
    __syncthreads();

    const float C0 = c0_s;
    double lsesum = 0.0;
    int buf = 0;

    // =================== persistent tile loop ===================
    for (; tile < NT; tile += GRID) {
        int nxt = tile + GRID;
        float* Acur = buf ? Abuf1 : Abuf0;
        float* Anxt = buf ? Abuf0 : Abuf1;
        if (nxt < NT) prefetch_tile(X, nxt, Anxt, tid);
        CP_COMMIT();
        CP_WAIT1();                  // current tile's data complete
        __syncthreads();

        float c[9][4];
        #pragma unroll
        for (int j = 0; j < 9; j++)
            { c[j][0] = 0.f; c[j][1] = 0.f; c[j][2] = 0.f; c[j][3] = 0.f; }

        const float*  aptr = Acur + (16 * wid + g) * ASTR + t4;
        const float4* bw   = (const float4*)B_s + lane;

        #pragma unroll
        for (int k0 = 0; k0 < 64; k0 += 8) {
            float f0 = aptr[k0];
            float f1 = aptr[8 * ASTR + k0];
            float f2 = aptr[k0 + 4];
            float f3 = aptr[8 * ASTR + k0 + 4];
            uint32_t a0 = __float_as_uint(f0), a1 = __float_as_uint(f1);
            uint32_t a2 = __float_as_uint(f2), a3 = __float_as_uint(f3);
            uint32_t q0 = __float_as_uint(tf32r(f0 * f0));
            uint32_t q1 = __float_as_uint(tf32r(f1 * f1));
            uint32_t q2 = __float_as_uint(tf32r(f2 * f2));
            uint32_t q3 = __float_as_uint(tf32r(f3 * f3));
            const int oct = k0 >> 3;
            #pragma unroll
            for (int j = 0; j < 9; j++) {
                float4 b = bw[(j * 8 + oct) * 32];
                mma8(c[j], a0, a1, a2, a3, __float_as_uint(b.x), __float_as_uint(b.y));
                mma8(c[j], q0, q1, q2, q3, __float_as_uint(b.z), __float_as_uint(b.w));
            }
        }

        // ---- epilogue: lp, logsumexp, stage into own A rows ----
        #pragma unroll
        for (int h = 0; h < 2; h++) {
            int r = 16 * wid + 8 * h + g;
            float bgq  = __shfl_sync(0xffffffffu, c[8][2 * h], lane & ~3);
            float lpbg = -0.5f * (C0 + bgq);
            float lp[16];
            float mx = -3.4e38f;
            #pragma unroll
            for (int j = 0; j < 8; j++) {
                int col = 8 * j + 2 * t4;
                float v0 = fmaf(-0.5f, c[j][2 * h],     offs_s[col])     + lpbg;
                float v1 = fmaf(-0.5f, c[j][2 * h + 1], offs_s[col + 1]) + lpbg;
                lp[2 * j] = v0; lp[2 * j + 1] = v1;
                mx = fmaxf(mx, fmaxf(v0 + lpi_s[col], v1 + lpi_s[col + 1]));
            }
            mx = fmaxf(mx, __shfl_xor_sync(0xffffffffu, mx, 1));
            mx = fmaxf(mx, __shfl_xor_sync(0xffffffffu, mx, 2));
            float se = 0.f;
            #pragma unroll
            for (int j = 0; j < 8; j++) {
                int col = 8 * j + 2 * t4;
                se += __expf(lp[2 * j]     + lpi_s[col]     - mx);
                se += __expf(lp[2 * j + 1] + lpi_s[col + 1] - mx);
            }
            se += __shfl_xor_sync(0xffffffffu, se, 1);
            se += __shfl_xor_sync(0xffffffffu, se, 2);
            if (t4 == 0) lsesum += (double)(mx + __logf(se));
            float* srow = Acur + r * ASTR + 2 * t4;
            #pragma unroll
            for (int j = 0; j < 8; j++)
                *(float2*)(srow + 8 * j) = make_float2(lp[2 * j], lp[2 * j + 1]);
        }
        __syncthreads();

        // ---- coalesced copy out (out+65 is 4B aligned -> scalar stores) ----
        float* obase = out + 65 + (size_t)tile * TM * Kk;
        #pragma unroll
        for (int i = 0; i < 32; i++) {
            int idx = tid + TPB * i;             // 8192 floats
            obase[idx] = Acur[(idx >> 6) * ASTR + (idx & 63)];
        }
        __syncthreads();                          // Acur free before its reuse as prefetch dst
        buf ^= 1;
    }

    // ---- loss reduce: one atomic per CTA, last CTA finalizes ----
    #pragma unroll
    for (int s = 16; s; s >>= 1)
        lsesum += __shfl_xor_sync(0xffffffffu, lsesum, s);
    if (lane == 0) wsum[wid] = lsesum;
    __syncthreads();
    if (tid == 0) {
        double bsum = 0.0;
        #pragma unroll
        for (int w = 0; w < TPB / 32; w++) bsum += wsum[w];
        atomicAdd(&g_lse, bsum);
        __threadfence();
        unsigned int old = atomicAdd(&g_count, 1u);
        if (old == GRID - 1) {
            __threadfence();
            double total = atomicAdd(&g_lse, 0.0);
            out[0] = (float)((double)kl_s * (double)Nn - total);
            g_lse = 0.0;              // deterministic graph replay
            g_count = 0u;
        }
    }
}

// ---------------------------------------------------------------------------
extern "C" void kernel_launch(void* const* d_in, const int* in_sizes, int n_in,
                              void* d_out, int out_size)
{
    const float* X  = (const float*)d_in[0];
    const float* u  = (const float*)d_in[1];
    const float* pl = (const float*)d_in[2];
    const float* mu = (const float*)d_in[3];
    const float* lv = (const float*)d_in[4];
    const float* pi = (const float*)d_in[5];
    const float* pp = (const float*)d_in[6];
    float* out = (float*)d_out;

    cudaFuncSetAttribute(gmm_kernel,
                         cudaFuncAttributeMaxDynamicSharedMemorySize, SMEM_BYTES);

    gmm_kernel<<<GRID, TPB, SMEM_BYTES>>>(X, u, pl, mu, lv, pi, pp, out);
}